// round 6
// baseline (speedup 1.0000x reference)
#include <cuda_runtime.h>
#include <cuda_bf16.h>
#include <math.h>
#include <stdint.h>

// Problem constants
constexpr int B  = 64;
constexpr int H  = 1024;
constexpr int E  = 1024;
constexpr int SEQ = 1024;
constexpr int V  = 50257;
constexpr long long BV = (long long)B * V;
constexpr int SPL = 8;                       // split-K for small GEMMs

// ---------------- scratch (static device memory; no allocs) ----------------
__device__ float g_gi[SPL * 3 * H * B];      // GRU input-gate partials  [split][row][b]
__device__ float g_gh[SPL * 3 * H * B];      // GRU hidden-gate partials
__device__ float g_hnew[B * H];              // new hidden state [b][h]
__device__ float g_pm[B * 16];               // attention chunk max
__device__ float g_pl[B * 16];               // attention chunk sum
__device__ float g_pctx[B * 16 * H];         // attention chunk context
__device__ float g_ctx[B * H];               // context [b][h]
__device__ float g_cpart[SPL * H * B];       // concat-gemm partials [split][n][b]
__device__ __nv_bfloat16 g_co_bf[B * H];     // concat_out (tanh) bf16 [b][n]

// ---------------- f32x2 packed-FMA helpers (sm_10x) ----------------
static __device__ __forceinline__ unsigned long long ffma2(
    unsigned long long a, unsigned long long b, unsigned long long c) {
    unsigned long long d;
    asm("fma.rn.f32x2 %0, %1, %2, %3;" : "=l"(d) : "l"(a), "l"(b), "l"(c));
    return d;
}
static __device__ __forceinline__ unsigned long long dup2(float x) {
    unsigned long long d;
    asm("mov.b64 %0, {%1, %1};" : "=l"(d) : "f"(x));
    return d;
}
static __device__ __forceinline__ float2 unpack2(unsigned long long v) {
    float2 r;
    asm("mov.b64 {%0, %1}, %2;" : "=f"(r.x), "=f"(r.y) : "l"(v));
    return r;
}
static __device__ __forceinline__ unsigned pack_bf2(float lo, float hi) {
    __nv_bfloat162 v = __floats2bfloat162_rn(lo, hi);
    return *reinterpret_cast<unsigned*>(&v);
}

// ---------------- tensor-core helpers (legacy mma.sync — valid on compute_103) ----------
static __device__ __forceinline__ void ldm_x4(unsigned& r0, unsigned& r1,
                                              unsigned& r2, unsigned& r3, const void* p) {
    unsigned addr = (unsigned)__cvta_generic_to_shared(p);
    asm volatile("ldmatrix.sync.aligned.m8n8.x4.shared.b16 {%0,%1,%2,%3}, [%4];"
                 : "=r"(r0), "=r"(r1), "=r"(r2), "=r"(r3) : "r"(addr));
}
static __device__ __forceinline__ void mma16816(float* d, const unsigned* a,
                                                unsigned b0, unsigned b1) {
    asm volatile(
        "mma.sync.aligned.m16n8k16.row.col.f32.bf16.bf16.f32 "
        "{%0,%1,%2,%3}, {%4,%5,%6,%7}, {%8,%9}, {%0,%1,%2,%3};"
        : "+f"(d[0]), "+f"(d[1]), "+f"(d[2]), "+f"(d[3])
        : "r"(a[0]), "r"(a[1]), "r"(a[2]), "r"(a[3]), "r"(b0), "r"(b1));
}

// ---------------- cp.async helpers ----------------
static __device__ __forceinline__ void cp16(uint32_t dst_smem, const void* src) {
    asm volatile("cp.async.cg.shared.global [%0], [%1], 16;"
                 :: "r"(dst_smem), "l"(src) : "memory");
}
#define CP_COMMIT() asm volatile("cp.async.commit_group;" ::: "memory")
#define CP_WAIT2()  asm volatile("cp.async.wait_group 2;" ::: "memory")

// ---------------- generic small tiled GEMM (fp32, FFMA2): C[64 x NTOT] = A @ W^T
template<int MODE, int NTOT, int KTOT, int SPLITS>
__global__ __launch_bounds__(256) void gemm64(
    const float* __restrict__ A,
    const int*   __restrict__ gidx,
    const float* __restrict__ emb,
    const float* __restrict__ Wm)
{
    __shared__ __align__(16) float As[16][64];
    __shared__ __align__(16) float Ws[16][256];
    __shared__ int sidx[64];

    const int t  = threadIdx.x;
    const int n0 = blockIdx.x * 256;
    constexpr int KSPL = KTOT / SPLITS;
    const int kstart = blockIdx.y * KSPL;

    if (MODE == 0) {
        if (t < 64) sidx[t] = gidx[t];
        __syncthreads();
    }

    unsigned long long acc[8][4];
    #pragma unroll
    for (int i = 0; i < 8; i++)
        #pragma unroll
        for (int j = 0; j < 4; j++) acc[i][j] = 0ull;

    const int tb  = t >> 5;
    const int tv  = t & 31;
    const int sb  = t & 63;
    const int skq = t >> 6;
    const int sr  = t >> 2;
    const int sfq = t & 3;

    for (int k0 = kstart; k0 < kstart + KSPL; k0 += 16) {
        {
            int kg = k0 + skq * 4;
            float4 v;
            if (MODE == 0) {
                const float* row = emb + (size_t)sidx[sb] * E;
                v = *(const float4*)(row + kg);
            } else if (MODE == 1) {
                v = *(const float4*)(A + sb * H + kg);
            } else {
                v = (kg < H) ? *(const float4*)(g_hnew + sb * H + kg)
                             : *(const float4*)(g_ctx  + sb * H + (kg - H));
            }
            As[skq*4+0][sb] = v.x; As[skq*4+1][sb] = v.y;
            As[skq*4+2][sb] = v.z; As[skq*4+3][sb] = v.w;
        }
        #pragma unroll
        for (int p = 0; p < 4; p++) {
            int r = p * 64 + sr;
            int n = n0 + r;
            float4 v = make_float4(0.f, 0.f, 0.f, 0.f);
            if ((NTOT % 256 == 0) || (n < NTOT))
                v = *(const float4*)(Wm + (size_t)n * KTOT + k0 + sfq * 4);
            Ws[sfq*4+0][r] = v.x; Ws[sfq*4+1][r] = v.y;
            Ws[sfq*4+2][r] = v.z; Ws[sfq*4+3][r] = v.w;
        }
        __syncthreads();

        #pragma unroll
        for (int kk = 0; kk < 16; kk++) {
            ulonglong2 aA = *(const ulonglong2*)(&As[kk][tb*8]);
            ulonglong2 aB = *(const ulonglong2*)(&As[kk][tb*8] + 4);
            float4 w0 = *(const float4*)(&Ws[kk][tv*8]);
            float4 w1 = *(const float4*)(&Ws[kk][tv*8] + 4);
            float wv[8] = {w0.x, w0.y, w0.z, w0.w, w1.x, w1.y, w1.z, w1.w};
            #pragma unroll
            for (int wi = 0; wi < 8; wi++) {
                unsigned long long w2 = dup2(wv[wi]);
                acc[wi][0] = ffma2(aA.x, w2, acc[wi][0]);
                acc[wi][1] = ffma2(aA.y, w2, acc[wi][1]);
                acc[wi][2] = ffma2(aB.x, w2, acc[wi][2]);
                acc[wi][3] = ffma2(aB.y, w2, acc[wi][3]);
            }
        }
        __syncthreads();
    }

    float* outp = (MODE == 0) ? g_gi : (MODE == 1) ? g_gh : g_cpart;
    #pragma unroll
    for (int wi = 0; wi < 8; wi++) {
        int n = n0 + tv * 8 + wi;
        if (n < NTOT) {
            float* o = outp + ((size_t)blockIdx.y * NTOT + n) * 64 + tb * 8;
            #pragma unroll
            for (int j = 0; j < 4; j++) {
                float2 c = unpack2(acc[wi][j]);
                o[2*j] = c.x; o[2*j + 1] = c.y;
            }
        }
    }
}

// ---------------- GRU gates ----------------
__global__ void gru_gates(const float* __restrict__ lh, const float* __restrict__ b_ih,
                          const float* __restrict__ b_hh, float* __restrict__ dout)
{
    int idx = blockIdx.x * 256 + threadIdx.x;
    int j = idx >> 6, b = idx & 63;
    float ir = 0.f, iz = 0.f, inn = 0.f, hr = 0.f, hz = 0.f, hn = 0.f;
    #pragma unroll
    for (int s = 0; s < SPL; s++) {
        const float* gi = g_gi + (size_t)s * (3 * H * 64);
        const float* gh = g_gh + (size_t)s * (3 * H * 64);
        ir  += gi[j*64 + b];            hr  += gh[j*64 + b];
        iz  += gi[(H + j)*64 + b];      hz  += gh[(H + j)*64 + b];
        inn += gi[(2*H + j)*64 + b];    hn  += gh[(2*H + j)*64 + b];
    }
    ir += b_ih[j]; iz += b_ih[H + j]; inn += b_ih[2*H + j];
    hr += b_hh[j]; hz += b_hh[H + j]; hn  += b_hh[2*H + j];
    float r = 1.f / (1.f + expf(-(ir + hr)));
    float z = 1.f / (1.f + expf(-(iz + hz)));
    float n = tanhf(inn + r * hn);
    float h = lh[b * H + j];
    float hnew = (1.f - z) * n + z * h;
    g_hnew[b * H + j] = hnew;
    dout[BV + (size_t)b * H + j] = hnew;
}

// ---------------- attention: single-pass per (b, chunk) with online softmax ----------------
__global__ __launch_bounds__(256) void attn_fused(const float* __restrict__ enc)
{
    __shared__ __align__(16) float hn[H];
    __shared__ __align__(16) float4 sbuf[8][256];
    __shared__ float sm[8], sl[8];
    const int t = threadIdx.x, lane = t & 31, w = t >> 5;
    const int sp = blockIdx.x, b = blockIdx.y;

    ((float4*)hn)[t] = ((const float4*)(g_hnew + (size_t)b * H))[t];
    __syncthreads();
    const float4* hn4 = (const float4*)hn;

    float m = -1e30f, l = 0.f;
    float4 ctx[8];
    #pragma unroll
    for (int k = 0; k < 8; k++) ctx[k] = make_float4(0.f, 0.f, 0.f, 0.f);

    for (int i = 0; i < 8; i++) {
        int s = sp * 64 + w * 8 + i;
        const float4* e4 = (const float4*)(enc + ((size_t)b * SEQ + s) * H);
        float4 ev[8];
        float a = 0.f;
        #pragma unroll
        for (int k = 0; k < 8; k++) {
            ev[k] = e4[lane + 32 * k];
            float4 hv = hn4[lane + 32 * k];
            a += ev[k].x*hv.x + ev[k].y*hv.y + ev[k].z*hv.z + ev[k].w*hv.w;
        }
        #pragma unroll
        for (int o = 16; o > 0; o >>= 1) a += __shfl_xor_sync(0xffffffffu, a, o);
        if (a > m) {
            float sc = __expf(m - a);
            l *= sc;
            #pragma unroll
            for (int k = 0; k < 8; k++) {
                ctx[k].x *= sc; ctx[k].y *= sc; ctx[k].z *= sc; ctx[k].w *= sc;
            }
            m = a;
        }
        float p = __expf(a - m);
        l += p;
        #pragma unroll
        for (int k = 0; k < 8; k++) {
            ctx[k].x += p * ev[k].x; ctx[k].y += p * ev[k].y;
            ctx[k].z += p * ev[k].z; ctx[k].w += p * ev[k].w;
        }
    }

    if (lane == 0) { sm[w] = m; sl[w] = l; }
    __syncthreads();
    float M = -1e30f;
    #pragma unroll
    for (int w2 = 0; w2 < 8; w2++) M = fmaxf(M, sm[w2]);
    float e = __expf(m - M);
    #pragma unroll
    for (int k = 0; k < 8; k++) {
        float4 v = ctx[k];
        sbuf[w][lane + 32 * k] = make_float4(v.x * e, v.y * e, v.z * e, v.w * e);
    }
    float L = 0.f;
    #pragma unroll
    for (int w2 = 0; w2 < 8; w2++) L += sl[w2] * __expf(sm[w2] - M);
    __syncthreads();

    float4 acc = make_float4(0.f, 0.f, 0.f, 0.f);
    #pragma unroll
    for (int w2 = 0; w2 < 8; w2++) {
        float4 v = sbuf[w2][t];
        acc.x += v.x; acc.y += v.y; acc.z += v.z; acc.w += v.w;
    }
    *(float4*)(g_pctx + ((size_t)(b * 16 + sp)) * H + t * 4) = acc;
    if (t == 0) { g_pm[b * 16 + sp] = M; g_pl[b * 16 + sp] = L; }
}

__global__ void attn_combine()
{
    const int b = blockIdx.x, t = threadIdx.x;
    float M = -1e30f;
    #pragma unroll
    for (int c = 0; c < 16; c++) M = fmaxf(M, g_pm[b * 16 + c]);
    float e[16]; float L = 0.f;
    #pragma unroll
    for (int c = 0; c < 16; c++) { e[c] = __expf(g_pm[b*16 + c] - M); L += g_pl[b*16 + c] * e[c]; }
    float inv = 1.f / L;
    int j4 = t * 4;
    float4 acc = make_float4(0.f, 0.f, 0.f, 0.f);
    #pragma unroll
    for (int c = 0; c < 16; c++) {
        float4 v = *(const float4*)(g_pctx + ((size_t)(b * 16 + c)) * H + j4);
        float wv = e[c];
        acc.x += wv * v.x; acc.y += wv * v.y; acc.z += wv * v.z; acc.w += wv * v.w;
    }
    *(float4*)(g_ctx + (size_t)b * H + j4) =
        make_float4(acc.x * inv, acc.y * inv, acc.z * inv, acc.w * inv);
}

// ---------------- concat-gemm combine: bias + tanh -> bf16 A ----------------
__global__ void cat_combine(const float* __restrict__ cbias)
{
    int idx = blockIdx.x * 256 + threadIdx.x;
    int n = idx >> 6, b = idx & 63;
    float s = cbias[n];
    #pragma unroll
    for (int sp = 0; sp < SPL; sp++) s += g_cpart[((size_t)sp * H + n) * 64 + b];
    g_co_bf[b * H + n] = __float2bfloat16(tanhf(s));
}

// ---------------- output GEMM: cp.async 3-deep pipeline + in-smem fp32->bf16 convert ----
constexpr int NB = 128;
constexpr int KC = 32;
constexpr uint32_t OFF_AS = 0, AS_STG = 5120;
constexpr uint32_t OFF_BS = 15360, BS_STG = 10240;
constexpr uint32_t OFF_BR = 35840, BR_STG = 18432;
constexpr uint32_t OFF_BIAS = 91136;
constexpr uint32_t OUT_SMEM = 91648;

__global__ __launch_bounds__(256) void out_gemm_cp(const float* __restrict__ ow,
                                                   const float* __restrict__ ob,
                                                   float* __restrict__ dout)
{
    extern __shared__ __align__(16) unsigned char dsm[];
    const uint32_t sbase = (uint32_t)__cvta_generic_to_shared(dsm);
    const int t = threadIdx.x, lane = t & 31, warp = t >> 5;
    const int n0 = blockIdx.x * NB;
    const int wm = warp & 1, wn = warp >> 1;     // warp tile: M32 x N32

    // bias tile
    if (t < NB) {
        int n = n0 + t;
        ((float*)(dsm + OFF_BIAS))[t] = (n < V) ? ob[n] : 0.f;
    }

    // loader precompute
    const int a_row = t >> 2, a_seg = t & 3;
    const uint32_t a_doff = OFF_AS + (uint32_t)(a_row * 80 + a_seg * 16);
    const __nv_bfloat16* a_src = g_co_bf + a_row * H + a_seg * 8;
    uint32_t br_doff[4]; const float* br_src[4];
    #pragma unroll
    for (int j = 0; j < 4; j++) {
        int c = t + 256 * j;
        int row = c >> 3, seg = c & 7;
        br_doff[j] = OFF_BR + (uint32_t)(row * 144 + seg * 16);
        int gr = n0 + row; if (gr >= V) gr = V - 1;
        br_src[j] = ow + (size_t)gr * 1024 + seg * 4;
    }

    auto issue_stage = [&](int s) {
        const int k0 = s * KC;
        const uint32_t stg = (uint32_t)(s % 3);
        cp16(sbase + a_doff + stg * AS_STG, a_src + k0);
        #pragma unroll
        for (int j = 0; j < 4; j++)
            cp16(sbase + br_doff[j] + stg * BR_STG, br_src[j] + k0);
    };

    float acc[2][4][4];
    #pragma unroll
    for (int i = 0; i < 2; i++)
        #pragma unroll
        for (int j = 0; j < 4; j++)
            #pragma unroll
            for (int r = 0; r < 4; r++) acc[i][j][r] = 0.f;

    issue_stage(0); CP_COMMIT();
    issue_stage(1); CP_COMMIT();
    issue_stage(2); CP_COMMIT();

    const int cv_row = t >> 1, cv_half = t & 1;

    for (int s = 0; s < H / KC; s++) {
        CP_WAIT2();
        __syncthreads();

        // convert Braw[s%3] (fp32) -> Bs[s%2] (bf16)
        {
            const unsigned char* src = dsm + OFF_BR + (uint32_t)(s % 3) * BR_STG
                                       + cv_row * 144 + cv_half * 64;
            const float4* s4 = (const float4*)src;
            float4 v0 = s4[0], v1 = s4[1], v2 = s4[2], v3 = s4[3];
            uint4 p0 = make_uint4(pack_bf2(v0.x, v0.y), pack_bf2(v0.z, v0.w),
                                  pack_bf2(v1.x, v1.y), pack_bf2(v1.z, v1.w));
            uint4 p1 = make_uint4(pack_bf2(v2.x, v2.y), pack_bf2(v2.z, v2.w),
                                  pack_bf2(v3.x, v3.y), pack_bf2(v3.z, v3.w));
            uint4* dst = (uint4*)(dsm + OFF_BS + (uint32_t)(s & 1) * BS_STG
                                  + cv_row * 80 + cv_half * 32);
            dst[0] = p0; dst[1] = p1;
        }
        __syncthreads();

        // compute from As[s%3] + Bs[s%2]
        {
            const unsigned char* As_p = dsm + OFF_AS + (uint32_t)(s % 3) * AS_STG;
            const unsigned char* Bs_p = dsm + OFF_BS + (uint32_t)(s & 1) * BS_STG;
            #pragma unroll
            for (int ks = 0; ks < 2; ks++) {
                unsigned afr[2][4];
                #pragma unroll
                for (int tm = 0; tm < 2; tm++) {
                    int row = wm * 32 + tm * 16 + ((lane >> 3) & 1) * 8 + (lane & 7);
                    int col = ks * 16 + (lane >> 4) * 8;
                    ldm_x4(afr[tm][0], afr[tm][1], afr[tm][2], afr[tm][3],
                           As_p + row * 80 + col * 2);
                }
                unsigned bfr[4][2];
                #pragma unroll
                for (int g = 0; g < 2; g++) {
                    int nrow = wn * 32 + g * 16 + (lane >> 4) * 8 + (lane & 7);
                    int col  = ks * 16 + ((lane >> 3) & 1) * 8;
                    unsigned r0, r1, r2, r3;
                    ldm_x4(r0, r1, r2, r3, Bs_p + nrow * 80 + col * 2);
                    bfr[g*2+0][0] = r0; bfr[g*2+0][1] = r1;
                    bfr[g*2+1][0] = r2; bfr[g*2+1][1] = r3;
                }
                #pragma unroll
                for (int tm = 0; tm < 2; tm++)
                    #pragma unroll
                    for (int tn = 0; tn < 4; tn++)
                        mma16816(acc[tm][tn], afr[tm], bfr[tn][0], bfr[tn][1]);
            }
        }
        __syncthreads();
        if (s + 3 < H / KC) issue_stage(s + 3);
        CP_COMMIT();
    }

    // epilogue: scatter with bias
    const float* sbias = (const float*)(dsm + OFF_BIAS);
    const int mrow  = wm * 32 + (lane >> 2);
    const int ncol0 = n0 + wn * 32 + 2 * (lane & 3);
    #pragma unroll
    for (int tm = 0; tm < 2; tm++) {
        #pragma unroll
        for (int tn = 0; tn < 4; tn++) {
            int r = mrow + tm * 16;
            int c = ncol0 + tn * 8;
            if (c < V) {
                float bb = sbias[c - n0];
                dout[(size_t)r * V + c]       = acc[tm][tn][0] + bb;
                dout[(size_t)(r + 8) * V + c] = acc[tm][tn][2] + bb;
            }
            if (c + 1 < V) {
                float bb = sbias[c + 1 - n0];
                dout[(size_t)r * V + c + 1]       = acc[tm][tn][1] + bb;
                dout[(size_t)(r + 8) * V + c + 1] = acc[tm][tn][3] + bb;
            }
        }
    }
}

// ---------------- fused log-softmax: online lse, then subtract (row L2-hot) ----------------
__global__ __launch_bounds__(256) void lsesub(float* __restrict__ dout)
{
    __shared__ float rm[256], rl[256];
    const int b = blockIdx.x, t = threadIdx.x;
    float* row = dout + (size_t)b * V;
    float m = -1e30f, s = 0.f;
    for (int v = t; v < V; v += 256) {
        float x = row[v];
        if (x > m) { s *= __expf(m - x); m = x; }
        s += __expf(x - m);
    }
    rm[t] = m; rl[t] = s; __syncthreads();
    for (int o = 128; o > 0; o >>= 1) {
        if (t < o) {
            float m2 = fmaxf(rm[t], rm[t + o]);
            rl[t] = rl[t] * __expf(rm[t] - m2) + rl[t + o] * __expf(rm[t + o] - m2);
            rm[t] = m2;
        }
        __syncthreads();
    }
    float lse = rm[0] + logf(rl[0]);
    for (int v = t; v < V; v += 256) row[v] -= lse;
}

// ---------------- launch ----------------
extern "C" void kernel_launch(void* const* d_in, const int* in_sizes, int n_in,
                              void* d_out, int out_size)
{
    const int*   seq = (const int*)  d_in[0];
    const float* lh  = (const float*)d_in[1];
    const float* enc = (const float*)d_in[2];
    const float* emb = (const float*)d_in[3];
    const float* wih = (const float*)d_in[4];
    const float* whh = (const float*)d_in[5];
    const float* bih = (const float*)d_in[6];
    const float* bhh = (const float*)d_in[7];
    const float* cw  = (const float*)d_in[8];
    const float* cb  = (const float*)d_in[9];
    const float* ow  = (const float*)d_in[10];
    const float* ob  = (const float*)d_in[11];
    float* dout = (float*)d_out;
    (void)in_sizes; (void)n_in; (void)out_size;

    static bool attr_done = false;
    if (!attr_done) {
        cudaFuncSetAttribute(out_gemm_cp,
                             cudaFuncAttributeMaxDynamicSharedMemorySize, OUT_SMEM);
        attr_done = true;
    }

    // GRU gate GEMMs (split-K = 8)
    gemm64<0, 3*H, E, SPL><<<dim3(12, SPL), 256>>>(nullptr, seq, emb, wih);
    gemm64<1, 3*H, H, SPL><<<dim3(12, SPL), 256>>>(lh, nullptr, nullptr, whh);
    gru_gates<<<256, 256>>>(lh, bih, bhh, dout);

    // attention (single HBM pass, registers hold the tile)
    attn_fused<<<dim3(16, 64), 256>>>(enc);
    attn_combine<<<64, 256>>>();

    // concat GEMM (split-K = 8) + tanh -> bf16
    gemm64<2, H, 2*H, SPL><<<dim3(4, SPL), 256>>>(nullptr, nullptr, nullptr, cw);
    cat_combine<<<256, 256>>>(cb);

    // output GEMM — LAUNCHED TWICE (idempotent) as a timing bisection probe:
    // T(out_gemm) = dur_us(this round) - ~272us baseline. Diagnostic round.
    out_gemm_cp<<<(V + NB - 1) / NB, 256, OUT_SMEM>>>(ow, ob, dout);
    out_gemm_cp<<<(V + NB - 1) / NB, 256, OUT_SMEM>>>(ow, ob, dout);

    // fused log-softmax
    lsesub<<<64, 256>>>(dout);
}

// round 7
// speedup vs baseline: 1.5212x; 1.5212x over previous
#include <cuda_runtime.h>
#include <cuda_bf16.h>
#include <math.h>
#include <stdint.h>

// Problem constants
constexpr int B  = 64;
constexpr int H  = 1024;
constexpr int E  = 1024;
constexpr int SEQ = 1024;
constexpr int V  = 50257;
constexpr long long BV = (long long)B * V;
constexpr int SPL = 8;                       // split-K for small GEMMs
constexpr int NB = 128;                      // out-gemm N tile
constexpr int NBLK  = (V + NB - 1) / NB;     // 393 col-blocks
constexpr int NBLKP = 400;                   // padded stride

// ---------------- scratch (static device memory; no allocs) ----------------
__device__ float g_gi[SPL * 3 * H * B];      // GRU input-gate partials  [split][row][b]
__device__ float g_gh[SPL * 3 * H * B];      // GRU hidden-gate partials
__device__ float g_hnew[B * H];              // new hidden state [b][h]
__device__ float g_pm[B * 16];               // attention chunk max
__device__ float g_pl[B * 16];               // attention chunk sum
__device__ float g_pctx[B * 16 * H];         // attention chunk context
__device__ float g_ctx[B * H];               // context [b][h]
__device__ float g_cpart[SPL * H * B];       // concat-gemm partials [split][n][b]
__device__ __nv_bfloat16 g_co_bf[B * H];     // concat_out (tanh) bf16 [b][n]
__device__ float2 g_plse[B * NBLKP];         // per-(row, colblock) softmax partials (m,l)

// ---------------- f32x2 packed-FMA helpers (sm_10x) ----------------
static __device__ __forceinline__ unsigned long long ffma2(
    unsigned long long a, unsigned long long b, unsigned long long c) {
    unsigned long long d;
    asm("fma.rn.f32x2 %0, %1, %2, %3;" : "=l"(d) : "l"(a), "l"(b), "l"(c));
    return d;
}
static __device__ __forceinline__ unsigned long long dup2(float x) {
    unsigned long long d;
    asm("mov.b64 %0, {%1, %1};" : "=l"(d) : "f"(x));
    return d;
}
static __device__ __forceinline__ float2 unpack2(unsigned long long v) {
    float2 r;
    asm("mov.b64 {%0, %1}, %2;" : "=f"(r.x), "=f"(r.y) : "l"(v));
    return r;
}
static __device__ __forceinline__ unsigned pack_bf2(float lo, float hi) {
    __nv_bfloat162 v = __floats2bfloat162_rn(lo, hi);
    return *reinterpret_cast<unsigned*>(&v);
}

// ---------------- tensor-core helpers (legacy mma.sync — valid on compute_103) ----------
static __device__ __forceinline__ void ldm_x4(unsigned& r0, unsigned& r1,
                                              unsigned& r2, unsigned& r3, const void* p) {
    unsigned addr = (unsigned)__cvta_generic_to_shared(p);
    asm volatile("ldmatrix.sync.aligned.m8n8.x4.shared.b16 {%0,%1,%2,%3}, [%4];"
                 : "=r"(r0), "=r"(r1), "=r"(r2), "=r"(r3) : "r"(addr));
}
static __device__ __forceinline__ void mma16816(float* d, const unsigned* a,
                                                unsigned b0, unsigned b1) {
    asm volatile(
        "mma.sync.aligned.m16n8k16.row.col.f32.bf16.bf16.f32 "
        "{%0,%1,%2,%3}, {%4,%5,%6,%7}, {%8,%9}, {%0,%1,%2,%3};"
        : "+f"(d[0]), "+f"(d[1]), "+f"(d[2]), "+f"(d[3])
        : "r"(a[0]), "r"(a[1]), "r"(a[2]), "r"(a[3]), "r"(b0), "r"(b1));
}

// ---------------- cp.async helpers ----------------
static __device__ __forceinline__ void cp16(uint32_t dst_smem, const void* src) {
    asm volatile("cp.async.cg.shared.global [%0], [%1], 16;"
                 :: "r"(dst_smem), "l"(src) : "memory");
}
#define CP_COMMIT() asm volatile("cp.async.commit_group;" ::: "memory")
#define CP_WAIT1()  asm volatile("cp.async.wait_group 1;" ::: "memory")

// ---------------- fused GRU gate GEMMs: z=0 -> gi (emb gather), z=1 -> gh (hidden) ------
__global__ __launch_bounds__(256) void gemm_pair(
    const int*   __restrict__ gidx,
    const float* __restrict__ emb,
    const float* __restrict__ lh,
    const float* __restrict__ wih,
    const float* __restrict__ whh)
{
    __shared__ __align__(16) float As[16][64];
    __shared__ __align__(16) float Ws[16][256];
    __shared__ int sidx[64];

    const int t  = threadIdx.x;
    const int n0 = blockIdx.x * 256;
    const int kstart = blockIdx.y * (H / SPL);
    const bool is_h = (blockIdx.z == 1);
    const float* Wm = is_h ? whh : wih;

    if (!is_h && t < 64) sidx[t] = gidx[t];
    __syncthreads();

    unsigned long long acc[8][4];
    #pragma unroll
    for (int i = 0; i < 8; i++)
        #pragma unroll
        for (int j = 0; j < 4; j++) acc[i][j] = 0ull;

    const int tb  = t >> 5;
    const int tv  = t & 31;
    const int sb  = t & 63;
    const int skq = t >> 6;
    const int sr  = t >> 2;
    const int sfq = t & 3;

    for (int k0 = kstart; k0 < kstart + H / SPL; k0 += 16) {
        {
            int kg = k0 + skq * 4;
            float4 v;
            if (!is_h) v = *(const float4*)(emb + (size_t)sidx[sb] * E + kg);
            else       v = *(const float4*)(lh + sb * H + kg);
            As[skq*4+0][sb] = v.x; As[skq*4+1][sb] = v.y;
            As[skq*4+2][sb] = v.z; As[skq*4+3][sb] = v.w;
        }
        #pragma unroll
        for (int p = 0; p < 4; p++) {
            int r = p * 64 + sr;
            float4 v = *(const float4*)(Wm + (size_t)(n0 + r) * H + k0 + sfq * 4);
            Ws[sfq*4+0][r] = v.x; Ws[sfq*4+1][r] = v.y;
            Ws[sfq*4+2][r] = v.z; Ws[sfq*4+3][r] = v.w;
        }
        __syncthreads();

        #pragma unroll
        for (int kk = 0; kk < 16; kk++) {
            ulonglong2 aA = *(const ulonglong2*)(&As[kk][tb*8]);
            ulonglong2 aB = *(const ulonglong2*)(&As[kk][tb*8] + 4);
            float4 w0 = *(const float4*)(&Ws[kk][tv*8]);
            float4 w1 = *(const float4*)(&Ws[kk][tv*8] + 4);
            float wv[8] = {w0.x, w0.y, w0.z, w0.w, w1.x, w1.y, w1.z, w1.w};
            #pragma unroll
            for (int wi = 0; wi < 8; wi++) {
                unsigned long long w2 = dup2(wv[wi]);
                acc[wi][0] = ffma2(aA.x, w2, acc[wi][0]);
                acc[wi][1] = ffma2(aA.y, w2, acc[wi][1]);
                acc[wi][2] = ffma2(aB.x, w2, acc[wi][2]);
                acc[wi][3] = ffma2(aB.y, w2, acc[wi][3]);
            }
        }
        __syncthreads();
    }

    float* outp = is_h ? g_gh : g_gi;
    #pragma unroll
    for (int wi = 0; wi < 8; wi++) {
        int n = n0 + tv * 8 + wi;
        float* o = outp + ((size_t)blockIdx.y * (3 * H) + n) * 64 + tb * 8;
        #pragma unroll
        for (int j = 0; j < 4; j++) {
            float2 c = unpack2(acc[wi][j]);
            o[2*j] = c.x; o[2*j + 1] = c.y;
        }
    }
}

// ---------------- concat GEMM (split-K, FFMA2): C[64 x H] = [hnew|ctx] @ cw^T -----------
__global__ __launch_bounds__(256) void gemm_cat(const float* __restrict__ Wm)
{
    __shared__ __align__(16) float As[16][64];
    __shared__ __align__(16) float Ws[16][256];

    const int t  = threadIdx.x;
    const int n0 = blockIdx.x * 256;
    const int kstart = blockIdx.y * (2 * H / SPL);

    unsigned long long acc[8][4];
    #pragma unroll
    for (int i = 0; i < 8; i++)
        #pragma unroll
        for (int j = 0; j < 4; j++) acc[i][j] = 0ull;

    const int tb  = t >> 5;
    const int tv  = t & 31;
    const int sb  = t & 63;
    const int skq = t >> 6;
    const int sr  = t >> 2;
    const int sfq = t & 3;

    for (int k0 = kstart; k0 < kstart + 2 * H / SPL; k0 += 16) {
        {
            int kg = k0 + skq * 4;
            float4 v = (kg < H) ? *(const float4*)(g_hnew + sb * H + kg)
                                : *(const float4*)(g_ctx  + sb * H + (kg - H));
            As[skq*4+0][sb] = v.x; As[skq*4+1][sb] = v.y;
            As[skq*4+2][sb] = v.z; As[skq*4+3][sb] = v.w;
        }
        #pragma unroll
        for (int p = 0; p < 4; p++) {
            int r = p * 64 + sr;
            float4 v = *(const float4*)(Wm + (size_t)(n0 + r) * (2 * H) + k0 + sfq * 4);
            Ws[sfq*4+0][r] = v.x; Ws[sfq*4+1][r] = v.y;
            Ws[sfq*4+2][r] = v.z; Ws[sfq*4+3][r] = v.w;
        }
        __syncthreads();

        #pragma unroll
        for (int kk = 0; kk < 16; kk++) {
            ulonglong2 aA = *(const ulonglong2*)(&As[kk][tb*8]);
            ulonglong2 aB = *(const ulonglong2*)(&As[kk][tb*8] + 4);
            float4 w0 = *(const float4*)(&Ws[kk][tv*8]);
            float4 w1 = *(const float4*)(&Ws[kk][tv*8] + 4);
            float wv[8] = {w0.x, w0.y, w0.z, w0.w, w1.x, w1.y, w1.z, w1.w};
            #pragma unroll
            for (int wi = 0; wi < 8; wi++) {
                unsigned long long w2 = dup2(wv[wi]);
                acc[wi][0] = ffma2(aA.x, w2, acc[wi][0]);
                acc[wi][1] = ffma2(aA.y, w2, acc[wi][1]);
                acc[wi][2] = ffma2(aB.x, w2, acc[wi][2]);
                acc[wi][3] = ffma2(aB.y, w2, acc[wi][3]);
            }
        }
        __syncthreads();
    }

    #pragma unroll
    for (int wi = 0; wi < 8; wi++) {
        int n = n0 + tv * 8 + wi;
        float* o = g_cpart + ((size_t)blockIdx.y * H + n) * 64 + tb * 8;
        #pragma unroll
        for (int j = 0; j < 4; j++) {
            float2 c = unpack2(acc[wi][j]);
            o[2*j] = c.x; o[2*j + 1] = c.y;
        }
    }
}

// ---------------- GRU gates ----------------
__global__ void gru_gates(const float* __restrict__ lh, const float* __restrict__ b_ih,
                          const float* __restrict__ b_hh, float* __restrict__ dout)
{
    int idx = blockIdx.x * 256 + threadIdx.x;
    int j = idx >> 6, b = idx & 63;
    float ir = 0.f, iz = 0.f, inn = 0.f, hr = 0.f, hz = 0.f, hn = 0.f;
    #pragma unroll
    for (int s = 0; s < SPL; s++) {
        const float* gi = g_gi + (size_t)s * (3 * H * 64);
        const float* gh = g_gh + (size_t)s * (3 * H * 64);
        ir  += gi[j*64 + b];            hr  += gh[j*64 + b];
        iz  += gi[(H + j)*64 + b];      hz  += gh[(H + j)*64 + b];
        inn += gi[(2*H + j)*64 + b];    hn  += gh[(2*H + j)*64 + b];
    }
    ir += b_ih[j]; iz += b_ih[H + j]; inn += b_ih[2*H + j];
    hr += b_hh[j]; hz += b_hh[H + j]; hn  += b_hh[2*H + j];
    float r = 1.f / (1.f + expf(-(ir + hr)));
    float z = 1.f / (1.f + expf(-(iz + hz)));
    float n = tanhf(inn + r * hn);
    float h = lh[b * H + j];
    float hnew = (1.f - z) * n + z * h;
    g_hnew[b * H + j] = hnew;
    dout[BV + (size_t)b * H + j] = hnew;
}

// ---------------- attention: single-pass per (b, chunk) with online softmax ----------------
__global__ __launch_bounds__(256) void attn_fused(const float* __restrict__ enc)
{
    __shared__ __align__(16) float hn[H];
    __shared__ __align__(16) float4 sbuf[8][256];
    __shared__ float sm[8], sl[8];
    const int t = threadIdx.x, lane = t & 31, w = t >> 5;
    const int sp = blockIdx.x, b = blockIdx.y;

    ((float4*)hn)[t] = ((const float4*)(g_hnew + (size_t)b * H))[t];
    __syncthreads();
    const float4* hn4 = (const float4*)hn;

    float m = -1e30f, l = 0.f;
    float4 ctx[8];
    #pragma unroll
    for (int k = 0; k < 8; k++) ctx[k] = make_float4(0.f, 0.f, 0.f, 0.f);

    for (int i = 0; i < 8; i++) {
        int s = sp * 64 + w * 8 + i;
        const float4* e4 = (const float4*)(enc + ((size_t)b * SEQ + s) * H);
        float4 ev[8];
        float a = 0.f;
        #pragma unroll
        for (int k = 0; k < 8; k++) {
            ev[k] = e4[lane + 32 * k];
            float4 hv = hn4[lane + 32 * k];
            a += ev[k].x*hv.x + ev[k].y*hv.y + ev[k].z*hv.z + ev[k].w*hv.w;
        }
        #pragma unroll
        for (int o = 16; o > 0; o >>= 1) a += __shfl_xor_sync(0xffffffffu, a, o);
        if (a > m) {
            float sc = __expf(m - a);
            l *= sc;
            #pragma unroll
            for (int k = 0; k < 8; k++) {
                ctx[k].x *= sc; ctx[k].y *= sc; ctx[k].z *= sc; ctx[k].w *= sc;
            }
            m = a;
        }
        float p = __expf(a - m);
        l += p;
        #pragma unroll
        for (int k = 0; k < 8; k++) {
            ctx[k].x += p * ev[k].x; ctx[k].y += p * ev[k].y;
            ctx[k].z += p * ev[k].z; ctx[k].w += p * ev[k].w;
        }
    }

    if (lane == 0) { sm[w] = m; sl[w] = l; }
    __syncthreads();
    float M = -1e30f;
    #pragma unroll
    for (int w2 = 0; w2 < 8; w2++) M = fmaxf(M, sm[w2]);
    float e = __expf(m - M);
    #pragma unroll
    for (int k = 0; k < 8; k++) {
        float4 v = ctx[k];
        sbuf[w][lane + 32 * k] = make_float4(v.x * e, v.y * e, v.z * e, v.w * e);
    }
    float L = 0.f;
    #pragma unroll
    for (int w2 = 0; w2 < 8; w2++) L += sl[w2] * __expf(sm[w2] - M);
    __syncthreads();

    float4 acc = make_float4(0.f, 0.f, 0.f, 0.f);
    #pragma unroll
    for (int w2 = 0; w2 < 8; w2++) {
        float4 v = sbuf[w2][t];
        acc.x += v.x; acc.y += v.y; acc.z += v.z; acc.w += v.w;
    }
    *(float4*)(g_pctx + ((size_t)(b * 16 + sp)) * H + t * 4) = acc;
    if (t == 0) { g_pm[b * 16 + sp] = M; g_pl[b * 16 + sp] = L; }
}

__global__ void attn_combine()
{
    const int b = blockIdx.x, t = threadIdx.x;
    float M = -1e30f;
    #pragma unroll
    for (int c = 0; c < 16; c++) M = fmaxf(M, g_pm[b * 16 + c]);
    float e[16]; float L = 0.f;
    #pragma unroll
    for (int c = 0; c < 16; c++) { e[c] = __expf(g_pm[b*16 + c] - M); L += g_pl[b*16 + c] * e[c]; }
    float inv = 1.f / L;
    int j4 = t * 4;
    float4 acc = make_float4(0.f, 0.f, 0.f, 0.f);
    #pragma unroll
    for (int c = 0; c < 16; c++) {
        float4 v = *(const float4*)(g_pctx + ((size_t)(b * 16 + c)) * H + j4);
        float wv = e[c];
        acc.x += wv * v.x; acc.y += wv * v.y; acc.z += wv * v.z; acc.w += wv * v.w;
    }
    *(float4*)(g_ctx + (size_t)b * H + j4) =
        make_float4(acc.x * inv, acc.y * inv, acc.z * inv, acc.w * inv);
}

// ---------------- concat-gemm combine: bias + tanh -> bf16 A ----------------
__global__ void cat_combine(const float* __restrict__ cbias)
{
    int idx = blockIdx.x * 256 + threadIdx.x;
    int n = idx >> 6, b = idx & 63;
    float s = cbias[n];
    #pragma unroll
    for (int sp = 0; sp < SPL; sp++) s += g_cpart[((size_t)sp * H + n) * 64 + b];
    g_co_bf[b * H + n] = __float2bfloat16(tanhf(s));
}

// ---------------- output GEMM: cp.async 2-stage pipeline, 3 CTAs/SM, lse partials -------
constexpr int KC = 32;
constexpr uint32_t OFF_AS = 0,      AS_STG = 5120;    // bf16 A, 2 stages
constexpr uint32_t OFF_BS = 10240,  BS_STG = 10240;   // bf16 B, 2 bufs
constexpr uint32_t OFF_BR = 30720,  BR_STG = 18432;   // fp32 B raw, 2 stages
constexpr uint32_t OFF_BIAS = 67584;
constexpr uint32_t OUT_SMEM = 68096;

__global__ __launch_bounds__(256, 3) void out_gemm_cp(const float* __restrict__ ow,
                                                      const float* __restrict__ ob,
                                                      float* __restrict__ dout)
{
    extern __shared__ __align__(16) unsigned char dsm[];
    const uint32_t sbase = (uint32_t)__cvta_generic_to_shared(dsm);
    const int t = threadIdx.x, lane = t & 31, warp = t >> 5;
    const int n0 = blockIdx.x * NB;
    const int wm = warp & 1, wn = warp >> 1;     // warp tile: M32 x N32

    if (t < NB) {
        int n = n0 + t;
        ((float*)(dsm + OFF_BIAS))[t] = (n < V) ? ob[n] : 0.f;
    }

    // loader precompute
    const int a_row = t >> 2, a_seg = t & 3;
    const uint32_t a_doff = OFF_AS + (uint32_t)(a_row * 80 + a_seg * 16);
    const __nv_bfloat16* a_src = g_co_bf + a_row * H + a_seg * 8;
    uint32_t br_doff[4]; const float* br_src[4];
    #pragma unroll
    for (int j = 0; j < 4; j++) {
        int c = t + 256 * j;
        int row = c >> 3, seg = c & 7;
        br_doff[j] = OFF_BR + (uint32_t)(row * 144 + seg * 16);
        int gr = n0 + row; if (gr >= V) gr = V - 1;
        br_src[j] = ow + (size_t)gr * 1024 + seg * 4;
    }

    auto issue_stage = [&](int s) {
        const int k0 = s * KC;
        const uint32_t stg = (uint32_t)(s & 1);
        cp16(sbase + a_doff + stg * AS_STG, a_src + k0);
        #pragma unroll
        for (int j = 0; j < 4; j++)
            cp16(sbase + br_doff[j] + stg * BR_STG, br_src[j] + k0);
    };

    float acc[2][4][4];
    #pragma unroll
    for (int i = 0; i < 2; i++)
        #pragma unroll
        for (int j = 0; j < 4; j++)
            #pragma unroll
            for (int r = 0; r < 4; r++) acc[i][j][r] = 0.f;

    issue_stage(0); CP_COMMIT();
    issue_stage(1); CP_COMMIT();

    const int cv_row = t >> 1, cv_half = t & 1;

    for (int s = 0; s < H / KC; s++) {
        CP_WAIT1();
        __syncthreads();

        // convert Braw[s&1] (fp32) -> Bs[s&1] (bf16)
        {
            const unsigned char* src = dsm + OFF_BR + (uint32_t)(s & 1) * BR_STG
                                       + cv_row * 144 + cv_half * 64;
            const float4* s4 = (const float4*)src;
            float4 v0 = s4[0], v1 = s4[1], v2 = s4[2], v3 = s4[3];
            uint4 p0 = make_uint4(pack_bf2(v0.x, v0.y), pack_bf2(v0.z, v0.w),
                                  pack_bf2(v1.x, v1.y), pack_bf2(v1.z, v1.w));
            uint4 p1 = make_uint4(pack_bf2(v2.x, v2.y), pack_bf2(v2.z, v2.w),
                                  pack_bf2(v3.x, v3.y), pack_bf2(v3.z, v3.w));
            uint4* dst = (uint4*)(dsm + OFF_BS + (uint32_t)(s & 1) * BS_STG
                                  + cv_row * 80 + cv_half * 32);
            dst[0] = p0; dst[1] = p1;
        }
        __syncthreads();

        // compute from As[s&1] + Bs[s&1]
        {
            const unsigned char* As_p = dsm + OFF_AS + (uint32_t)(s & 1) * AS_STG;
            const unsigned char* Bs_p = dsm + OFF_BS + (uint32_t)(s & 1) * BS_STG;
            #pragma unroll
            for (int ks = 0; ks < 2; ks++) {
                unsigned afr[2][4];
                #pragma unroll
                for (int tm = 0; tm < 2; tm++) {
                    int row = wm * 32 + tm * 16 + ((lane >> 3) & 1) * 8 + (lane & 7);
                    int col = ks * 16 + (lane >> 4) * 8;
                    ldm_x4(afr[tm][0], afr[tm][1], afr[tm][2], afr[tm][3],
                           As_p + row * 80 + col * 2);
                }
                unsigned bfr[4][2];
                #pragma unroll
                for (int g = 0; g < 2; g++) {
                    int nrow = wn * 32 + g * 16 + (lane >> 4) * 8 + (lane & 7);
                    int col  = ks * 16 + ((lane >> 3) & 1) * 8;
                    unsigned r0, r1, r2, r3;
                    ldm_x4(r0, r1, r2, r3, Bs_p + nrow * 80 + col * 2);
                    bfr[g*2+0][0] = r0; bfr[g*2+0][1] = r1;
                    bfr[g*2+1][0] = r2; bfr[g*2+1][1] = r3;
                }
                #pragma unroll
                for (int tm = 0; tm < 2; tm++)
                    #pragma unroll
                    for (int tn = 0; tn < 4; tn++)
                        mma16816(acc[tm][tn], afr[tm], bfr[tn][0], bfr[tn][1]);
            }
        }
        __syncthreads();
        if (s + 2 < H / KC) issue_stage(s + 2);
        CP_COMMIT();
    }

    // epilogue: write logits + per-(row, block) online-softmax partials
    const float* sbias = (const float*)(dsm + OFF_BIAS);
    float2* part = (float2*)dsm;                 // reuse As region (2KB)
    const int mrow  = wm * 32 + (lane >> 2);
    const int ncol0 = n0 + wn * 32 + 2 * (lane & 3);

    float pmv[4], plv[4];
    #pragma unroll
    for (int i = 0; i < 4; i++) { pmv[i] = -1e30f; plv[i] = 0.f; }

    #pragma unroll
    for (int tm = 0; tm < 2; tm++) {
        #pragma unroll
        for (int tn = 0; tn < 4; tn++) {
            int r = mrow + tm * 16;
            int c = ncol0 + tn * 8;
            #pragma unroll
            for (int cc = 0; cc < 2; cc++) {
                if (c + cc < V) {
                    float bb = sbias[c + cc - n0];
                    float v0 = acc[tm][tn][cc]     + bb;    // row r
                    float v1 = acc[tm][tn][2 + cc] + bb;    // row r+8
                    dout[(size_t)r * V + c + cc]       = v0;
                    dout[(size_t)(r + 8) * V + c + cc] = v1;
                    int i0 = 2 * tm, i1 = 2 * tm + 1;
                    if (v0 > pmv[i0]) { plv[i0] *= __expf(pmv[i0] - v0); pmv[i0] = v0; }
                    plv[i0] += __expf(v0 - pmv[i0]);
                    if (v1 > pmv[i1]) { plv[i1] *= __expf(pmv[i1] - v1); pmv[i1] = v1; }
                    plv[i1] += __expf(v1 - pmv[i1]);
                }
            }
        }
    }
    // reduce across the 4 lanes sharing each row (lane&3 varies cols only)
    #pragma unroll
    for (int i = 0; i < 4; i++) {
        #pragma unroll
        for (int off = 1; off <= 2; off <<= 1) {
            float om = __shfl_xor_sync(0xffffffffu, pmv[i], off);
            float ol = __shfl_xor_sync(0xffffffffu, plv[i], off);
            float nm = fmaxf(pmv[i], om);
            plv[i] = plv[i] * __expf(pmv[i] - nm) + ol * __expf(om - nm);
            pmv[i] = nm;
        }
    }
    if ((lane & 3) == 0) {
        #pragma unroll
        for (int i = 0; i < 4; i++) {
            int row = wm * 32 + (lane >> 2) + (i & 1) * 8 + (i >> 1) * 16;
            part[row * 4 + wn] = make_float2(pmv[i], plv[i]);
        }
    }
    __syncthreads();
    if (t < 64) {
        float m = -1e30f, l = 0.f;
        #pragma unroll
        for (int k = 0; k < 4; k++) {
            float2 p = part[t * 4 + k];
            float nm = fmaxf(m, p.x);
            l = l * __expf(m - nm) + p.y * __expf(p.x - nm);
            m = nm;
        }
        g_plse[t * NBLKP + blockIdx.x] = make_float2(m, l);
    }
}

// ---------------- final: reduce lse partials (redundantly per CTA) + subtract ----------
constexpr int SUBSPAN = 6288;   // 8 * 6288 >= V
__global__ __launch_bounds__(256) void sub_final(float* __restrict__ dout)
{
    __shared__ float rm[256], rl[256];
    const int b = blockIdx.y, cx = blockIdx.x, t = threadIdx.x;
    float m = -1e30f, l = 0.f;
    for (int i = t; i < NBLK; i += 256) {
        float2 p = g_plse[b * NBLKP + i];
        float nm = fmaxf(m, p.x);
        l = l * __expf(m - nm) + p.y * __expf(p.x - nm);
        m = nm;
    }
    rm[t] = m; rl[t] = l; __syncthreads();
    for (int o = 128; o > 0; o >>= 1) {
        if (t < o) {
            float m2 = fmaxf(rm[t], rm[t + o]);
            rl[t] = rl[t] * __expf(rm[t] - m2) + rl[t + o] * __expf(rm[t + o] - m2);
            rm[t] = m2;
        }
        __syncthreads();
    }
    float lse = rm[0] + logf(rl[0]);
    float* row = dout + (size_t)b * V;
    int end = cx * SUBSPAN + SUBSPAN; if (end > V) end = V;
    for (int v = cx * SUBSPAN + t; v < end; v += 256) row[v] -= lse;
}

// ---------------- launch ----------------
extern "C" void kernel_launch(void* const* d_in, const int* in_sizes, int n_in,
                              void* d_out, int out_size)
{
    const int*   seq = (const int*)  d_in[0];
    const float* lh  = (const float*)d_in[1];
    const float* enc = (const float*)d_in[2];
    const float* emb = (const float*)d_in[3];
    const float* wih = (const float*)d_in[4];
    const float* whh = (const float*)d_in[5];
    const float* bih = (const float*)d_in[6];
    const float* bhh = (const float*)d_in[7];
    const float* cw  = (const float*)d_in[8];
    const float* cb  = (const float*)d_in[9];
    const float* ow  = (const float*)d_in[10];
    const float* ob  = (const float*)d_in[11];
    float* dout = (float*)d_out;
    (void)in_sizes; (void)n_in; (void)out_size;

    static bool attr_done = false;
    if (!attr_done) {
        cudaFuncSetAttribute(out_gemm_cp,
                             cudaFuncAttributeMaxDynamicSharedMemorySize, OUT_SMEM);
        attr_done = true;
    }

    // fused GRU gate GEMMs (z=0: emb path, z=1: hidden path)
    gemm_pair<<<dim3(12, SPL, 2), 256>>>(seq, emb, lh, wih, whh);
    gru_gates<<<256, 256>>>(lh, bih, bhh, dout);

    // attention (single HBM pass)
    attn_fused<<<dim3(16, 64), 256>>>(enc);
    attn_combine<<<64, 256>>>();

    // concat GEMM + tanh -> bf16
    gemm_cat<<<dim3(4, SPL), 256>>>(cw);
    cat_combine<<<256, 256>>>(cb);

    // output GEMM (mma.sync + cp.async, 3 CTA/SM) -> logits + lse partials
    out_gemm_cp<<<NBLK, 256, OUT_SMEM>>>(ow, ob, dout);

    // reduce partials + subtract (full-chip)
    sub_final<<<dim3(8, 64), 256>>>(dout);
}

// round 8
// speedup vs baseline: 2.3541x; 1.5475x over previous
#include <cuda_runtime.h>
#include <cuda_bf16.h>
#include <math.h>
#include <stdint.h>

// Problem constants
constexpr int B  = 64;
constexpr int H  = 1024;
constexpr int E  = 1024;
constexpr int SEQ = 1024;
constexpr int V  = 50257;
constexpr long long BV = (long long)B * V;
constexpr int SPL = 8;                       // split-K for GRU gate GEMMs
constexpr int CATSPL = 16;                   // split-K for concat GEMM
constexpr int NB = 128;                      // out-gemm N tile
constexpr int NBLK  = (V + NB - 1) / NB;     // 393 col-blocks
constexpr int NBLKP = 400;                   // padded stride

// ---------------- scratch (static device memory; no allocs) ----------------
__device__ float g_gi[SPL * 3 * H * B];      // GRU input-gate partials  [split][row][b]
__device__ float g_gh[SPL * 3 * H * B];      // GRU hidden-gate partials
__device__ float g_hnew[B * H];              // new hidden state [b][h]
__device__ float g_pm[B * 16];               // attention chunk max
__device__ float g_pl[B * 16];               // attention chunk sum
__device__ float g_pctx[B * 16 * H];         // attention chunk context
__device__ float g_ctx[B * H];               // context [b][h]
__device__ float g_cpart[CATSPL * H * B];    // concat-gemm partials [split][n][b]
__device__ __nv_bfloat16 g_co_bf[B * H];     // concat_out (tanh) bf16 [b][n]
__device__ float2 g_plse[B * NBLKP];         // per-(row, colblock) softmax partials (m,l)

// ---------------- helpers ----------------
static __device__ __forceinline__ unsigned pack_bf2(float lo, float hi) {
    __nv_bfloat162 v = __floats2bfloat162_rn(lo, hi);
    return *reinterpret_cast<unsigned*>(&v);
}
static __device__ __forceinline__ void ldm_x4(unsigned& r0, unsigned& r1,
                                              unsigned& r2, unsigned& r3, const void* p) {
    unsigned addr = (unsigned)__cvta_generic_to_shared(p);
    asm volatile("ldmatrix.sync.aligned.m8n8.x4.shared.b16 {%0,%1,%2,%3}, [%4];"
                 : "=r"(r0), "=r"(r1), "=r"(r2), "=r"(r3) : "r"(addr));
}
static __device__ __forceinline__ void mma16816(float* d, const unsigned* a,
                                                unsigned b0, unsigned b1) {
    asm volatile(
        "mma.sync.aligned.m16n8k16.row.col.f32.bf16.bf16.f32 "
        "{%0,%1,%2,%3}, {%4,%5,%6,%7}, {%8,%9}, {%0,%1,%2,%3};"
        : "+f"(d[0]), "+f"(d[1]), "+f"(d[2]), "+f"(d[3])
        : "r"(a[0]), "r"(a[1]), "r"(a[2]), "r"(a[3]), "r"(b0), "r"(b1));
}
static __device__ __forceinline__ void cp16(uint32_t dst_smem, const void* src) {
    asm volatile("cp.async.cg.shared.global [%0], [%1], 16;"
                 :: "r"(dst_smem), "l"(src) : "memory");
}
#define CP_COMMIT() asm volatile("cp.async.commit_group;" ::: "memory")
#define CP_WAIT1()  asm volatile("cp.async.wait_group 1;" ::: "memory")

// ---------------- small mma GEMMs: C[64 x NTOT] = A[64 x KTOT] @ W[NTOT x KTOT]^T ------
// MODE 0: GRU pair (blockIdx.z: 0 -> gi with emb gather, 1 -> gh with last_hidden)
// MODE 2: concat GEMM (A = [hnew | ctx])
// Writes fp32 split-K partials [split][n][64b]. KSPAN=128 per split (4 cp.async stages).
template<int MODE, int NTOT, int KTOT, int SPLITS>
__global__ __launch_bounds__(256) void mma_small(
    const int*   __restrict__ gidx,
    const float* __restrict__ emb,
    const float* __restrict__ lh,
    const float* __restrict__ w0,
    const float* __restrict__ w1)
{
    constexpr int KSPAN = KTOT / SPLITS;      // 128
    constexpr int NST   = KSPAN / 32;         // 4
    constexpr int ASTR  = KSPAN * 2 + 16;     // 272 B row stride (bf16 A)
    constexpr uint32_t OFF_BR2 = 64u * ASTR;            // 17408
    constexpr uint32_t OFF_BS2 = OFF_BR2 + 2u * 18432;  // 54272
    // total smem = OFF_BS2 + 10240 = 64512

    extern __shared__ __align__(16) unsigned char dsm[];
    __shared__ int sidx[64];
    const uint32_t sbase = (uint32_t)__cvta_generic_to_shared(dsm);
    const int t = threadIdx.x, lane = t & 31, warp = t >> 5;
    const int wm = warp & 1, wn = warp >> 1;
    const int n0 = blockIdx.x * 128;
    const int kstart = blockIdx.y * KSPAN;
    const bool is_h = (MODE == 0) && (blockIdx.z == 1);
    const float* Wm = (MODE == 0) ? (is_h ? w1 : w0) : w0;

    if (MODE == 0 && !is_h && t < 64) sidx[t] = gidx[t];
    __syncthreads();

    // ---- preload A slice [64 x KSPAN] fp32 -> bf16 smem ----
    {
        int row = t >> 2, seg = t & 3;
        const float* asrc;
        if (MODE == 0)
            asrc = is_h ? (lh + row * H + kstart)
                        : (emb + (size_t)sidx[row] * E + kstart);
        else
            asrc = (kstart < H) ? (g_hnew + row * H + kstart)
                                : (g_ctx  + row * H + kstart - H);
        unsigned char* adst = dsm + row * ASTR;
        #pragma unroll
        for (int q = 0; q < KSPAN / 16; q++) {            // 8 float4 per thread
            int c = seg * (KSPAN / 4) + q * 4;
            float4 v = *(const float4*)(asrc + c);
            *(uint2*)(adst + c * 2) =
                make_uint2(pack_bf2(v.x, v.y), pack_bf2(v.z, v.w));
        }
    }

    // ---- B loader precompute (128 rows x 32 fp32 per stage) ----
    uint32_t br_doff[4]; const float* br_src[4];
    #pragma unroll
    for (int j = 0; j < 4; j++) {
        int c = t + 256 * j;
        int row = c >> 3, seg = c & 7;
        br_doff[j] = OFF_BR2 + (uint32_t)(row * 144 + seg * 16);
        br_src[j] = Wm + (size_t)(n0 + row) * KTOT + kstart + seg * 4;
    }
    auto issue_stage = [&](int s) {
        #pragma unroll
        for (int j = 0; j < 4; j++)
            cp16(sbase + br_doff[j] + (uint32_t)(s & 1) * 18432u, br_src[j] + s * 32);
    };

    float acc[2][4][4];
    #pragma unroll
    for (int i = 0; i < 2; i++)
        #pragma unroll
        for (int j = 0; j < 4; j++)
            #pragma unroll
            for (int r = 0; r < 4; r++) acc[i][j][r] = 0.f;

    issue_stage(0); CP_COMMIT();
    issue_stage(1); CP_COMMIT();
    __syncthreads();   // A preload visible before compute

    const int cv_row = t >> 1, cv_half = t & 1;

    for (int s = 0; s < NST; s++) {
        CP_WAIT1();
        __syncthreads();
        // convert Br[s&1] fp32 -> Bs bf16 (single buffer)
        {
            const unsigned char* src = dsm + OFF_BR2 + (uint32_t)(s & 1) * 18432u
                                       + cv_row * 144 + cv_half * 64;
            const float4* s4 = (const float4*)src;
            float4 v0 = s4[0], v1 = s4[1], v2 = s4[2], v3 = s4[3];
            uint4 p0 = make_uint4(pack_bf2(v0.x, v0.y), pack_bf2(v0.z, v0.w),
                                  pack_bf2(v1.x, v1.y), pack_bf2(v1.z, v1.w));
            uint4 p1 = make_uint4(pack_bf2(v2.x, v2.y), pack_bf2(v2.z, v2.w),
                                  pack_bf2(v3.x, v3.y), pack_bf2(v3.z, v3.w));
            uint4* dst = (uint4*)(dsm + OFF_BS2 + cv_row * 80 + cv_half * 32);
            dst[0] = p0; dst[1] = p1;
        }
        __syncthreads();
        // compute: A cols s*32..s*32+31 vs Bs
        #pragma unroll
        for (int ks = 0; ks < 2; ks++) {
            unsigned afr[2][4];
            #pragma unroll
            for (int tm = 0; tm < 2; tm++) {
                int row = wm * 32 + tm * 16 + ((lane >> 3) & 1) * 8 + (lane & 7);
                int col = s * 32 + ks * 16 + (lane >> 4) * 8;
                ldm_x4(afr[tm][0], afr[tm][1], afr[tm][2], afr[tm][3],
                       dsm + row * ASTR + col * 2);
            }
            unsigned bfr[4][2];
            #pragma unroll
            for (int g = 0; g < 2; g++) {
                int nrow = wn * 32 + g * 16 + (lane >> 4) * 8 + (lane & 7);
                int col  = ks * 16 + ((lane >> 3) & 1) * 8;
                unsigned r0, r1, r2, r3;
                ldm_x4(r0, r1, r2, r3, dsm + OFF_BS2 + nrow * 80 + col * 2);
                bfr[g*2+0][0] = r0; bfr[g*2+0][1] = r1;
                bfr[g*2+1][0] = r2; bfr[g*2+1][1] = r3;
            }
            #pragma unroll
            for (int tm = 0; tm < 2; tm++)
                #pragma unroll
                for (int tn = 0; tn < 4; tn++)
                    mma16816(acc[tm][tn], afr[tm], bfr[tn][0], bfr[tn][1]);
        }
        __syncthreads();
        if (s + 2 < NST) issue_stage(s + 2);
        CP_COMMIT();
    }

    // ---- epilogue: fp32 split-K partials [split][n][64b] ----
    float* outp = (MODE == 0) ? (is_h ? g_gh : g_gi) : g_cpart;
    const size_t base = (size_t)blockIdx.y * NTOT * 64;
    const int mrow  = wm * 32 + (lane >> 2);
    const int ncol0 = wn * 32 + 2 * (lane & 3);
    #pragma unroll
    for (int tm = 0; tm < 2; tm++) {
        #pragma unroll
        for (int tn = 0; tn < 4; tn++) {
            #pragma unroll
            for (int cc = 0; cc < 2; cc++) {
                int n = n0 + ncol0 + tn * 8 + cc;
                float* o = outp + base + (size_t)n * 64;
                o[mrow + tm * 16]     = acc[tm][tn][cc];
                o[mrow + tm * 16 + 8] = acc[tm][tn][2 + cc];
            }
        }
    }
}
constexpr uint32_t SMALL_SMEM = 64512;

// ---------------- GRU gates ----------------
__global__ void gru_gates(const float* __restrict__ lh, const float* __restrict__ b_ih,
                          const float* __restrict__ b_hh, float* __restrict__ dout)
{
    int idx = blockIdx.x * 256 + threadIdx.x;
    int j = idx >> 6, b = idx & 63;
    float ir = 0.f, iz = 0.f, inn = 0.f, hr = 0.f, hz = 0.f, hn = 0.f;
    #pragma unroll
    for (int s = 0; s < SPL; s++) {
        const float* gi = g_gi + (size_t)s * (3 * H * 64);
        const float* gh = g_gh + (size_t)s * (3 * H * 64);
        ir  += gi[j*64 + b];            hr  += gh[j*64 + b];
        iz  += gi[(H + j)*64 + b];      hz  += gh[(H + j)*64 + b];
        inn += gi[(2*H + j)*64 + b];    hn  += gh[(2*H + j)*64 + b];
    }
    ir += b_ih[j]; iz += b_ih[H + j]; inn += b_ih[2*H + j];
    hr += b_hh[j]; hz += b_hh[H + j]; hn  += b_hh[2*H + j];
    float r = 1.f / (1.f + expf(-(ir + hr)));
    float z = 1.f / (1.f + expf(-(iz + hz)));
    float n = tanhf(inn + r * hn);
    float h = lh[b * H + j];
    float hnew = (1.f - z) * n + z * h;
    g_hnew[b * H + j] = hnew;
    dout[BV + (size_t)b * H + j] = hnew;
}

// ---------------- attention: single-pass per (b, chunk) with online softmax ----------------
__global__ __launch_bounds__(256) void attn_fused(const float* __restrict__ enc)
{
    __shared__ __align__(16) float hn[H];
    __shared__ __align__(16) float4 sbuf[8][256];
    __shared__ float sm[8], sl[8];
    const int t = threadIdx.x, lane = t & 31, w = t >> 5;
    const int sp = blockIdx.x, b = blockIdx.y;

    ((float4*)hn)[t] = ((const float4*)(g_hnew + (size_t)b * H))[t];
    __syncthreads();
    const float4* hn4 = (const float4*)hn;

    float m = -1e30f, l = 0.f;
    float4 ctx[8];
    #pragma unroll
    for (int k = 0; k < 8; k++) ctx[k] = make_float4(0.f, 0.f, 0.f, 0.f);

    for (int i = 0; i < 8; i++) {
        int s = sp * 64 + w * 8 + i;
        const float4* e4 = (const float4*)(enc + ((size_t)b * SEQ + s) * H);
        float4 ev[8];
        float a = 0.f;
        #pragma unroll
        for (int k = 0; k < 8; k++) {
            ev[k] = e4[lane + 32 * k];
            float4 hv = hn4[lane + 32 * k];
            a += ev[k].x*hv.x + ev[k].y*hv.y + ev[k].z*hv.z + ev[k].w*hv.w;
        }
        #pragma unroll
        for (int o = 16; o > 0; o >>= 1) a += __shfl_xor_sync(0xffffffffu, a, o);
        if (a > m) {
            float sc = __expf(m - a);
            l *= sc;
            #pragma unroll
            for (int k = 0; k < 8; k++) {
                ctx[k].x *= sc; ctx[k].y *= sc; ctx[k].z *= sc; ctx[k].w *= sc;
            }
            m = a;
        }
        float p = __expf(a - m);
        l += p;
        #pragma unroll
        for (int k = 0; k < 8; k++) {
            ctx[k].x += p * ev[k].x; ctx[k].y += p * ev[k].y;
            ctx[k].z += p * ev[k].z; ctx[k].w += p * ev[k].w;
        }
    }

    if (lane == 0) { sm[w] = m; sl[w] = l; }
    __syncthreads();
    float M = -1e30f;
    #pragma unroll
    for (int w2 = 0; w2 < 8; w2++) M = fmaxf(M, sm[w2]);
    float e = __expf(m - M);
    #pragma unroll
    for (int k = 0; k < 8; k++) {
        float4 v = ctx[k];
        sbuf[w][lane + 32 * k] = make_float4(v.x * e, v.y * e, v.z * e, v.w * e);
    }
    float L = 0.f;
    #pragma unroll
    for (int w2 = 0; w2 < 8; w2++) L += sl[w2] * __expf(sm[w2] - M);
    __syncthreads();

    float4 acc = make_float4(0.f, 0.f, 0.f, 0.f);
    #pragma unroll
    for (int w2 = 0; w2 < 8; w2++) {
        float4 v = sbuf[w2][t];
        acc.x += v.x; acc.y += v.y; acc.z += v.z; acc.w += v.w;
    }
    *(float4*)(g_pctx + ((size_t)(b * 16 + sp)) * H + t * 4) = acc;
    if (t == 0) { g_pm[b * 16 + sp] = M; g_pl[b * 16 + sp] = L; }
}

__global__ void attn_combine()
{
    const int b = blockIdx.x, t = threadIdx.x;
    float M = -1e30f;
    #pragma unroll
    for (int c = 0; c < 16; c++) M = fmaxf(M, g_pm[b * 16 + c]);
    float e[16]; float L = 0.f;
    #pragma unroll
    for (int c = 0; c < 16; c++) { e[c] = __expf(g_pm[b*16 + c] - M); L += g_pl[b*16 + c] * e[c]; }
    float inv = 1.f / L;
    int j4 = t * 4;
    float4 acc = make_float4(0.f, 0.f, 0.f, 0.f);
    #pragma unroll
    for (int c = 0; c < 16; c++) {
        float4 v = *(const float4*)(g_pctx + ((size_t)(b * 16 + c)) * H + j4);
        float wv = e[c];
        acc.x += wv * v.x; acc.y += wv * v.y; acc.z += wv * v.z; acc.w += wv * v.w;
    }
    *(float4*)(g_ctx + (size_t)b * H + j4) =
        make_float4(acc.x * inv, acc.y * inv, acc.z * inv, acc.w * inv);
}

// ---------------- concat-gemm combine: bias + tanh -> bf16 A ----------------
__global__ void cat_combine(const float* __restrict__ cbias)
{
    int idx = blockIdx.x * 256 + threadIdx.x;
    int n = idx >> 6, b = idx & 63;
    float s = cbias[n];
    #pragma unroll
    for (int sp = 0; sp < CATSPL; sp++) s += g_cpart[((size_t)sp * H + n) * 64 + b];
    g_co_bf[b * H + n] = __float2bfloat16(tanhf(s));
}

// ---------------- output GEMM: cp.async 2-stage pipeline, 3 CTAs/SM, lse partials -------
constexpr int KC = 32;
constexpr uint32_t OFF_AS = 0,      AS_STG = 5120;    // bf16 A, 2 stages
constexpr uint32_t OFF_BS = 10240,  BS_STG = 10240;   // bf16 B, 2 bufs
constexpr uint32_t OFF_BR = 30720,  BR_STG = 18432;   // fp32 B raw, 2 stages
constexpr uint32_t OFF_BIAS = 67584;
constexpr uint32_t OUT_SMEM = 68096;

__global__ __launch_bounds__(256, 3) void out_gemm_cp(const float* __restrict__ ow,
                                                      const float* __restrict__ ob,
                                                      float* __restrict__ dout)
{
    extern __shared__ __align__(16) unsigned char dsm[];
    const uint32_t sbase = (uint32_t)__cvta_generic_to_shared(dsm);
    const int t = threadIdx.x, lane = t & 31, warp = t >> 5;
    const int n0 = blockIdx.x * NB;
    const int wm = warp & 1, wn = warp >> 1;     // warp tile: M32 x N32

    if (t < NB) {
        int n = n0 + t;
        ((float*)(dsm + OFF_BIAS))[t] = (n < V) ? ob[n] : 0.f;
    }

    // loader precompute
    const int a_row = t >> 2, a_seg = t & 3;
    const uint32_t a_doff = OFF_AS + (uint32_t)(a_row * 80 + a_seg * 16);
    const __nv_bfloat16* a_src = g_co_bf + a_row * H + a_seg * 8;
    uint32_t br_doff[4]; const float* br_src[4];
    #pragma unroll
    for (int j = 0; j < 4; j++) {
        int c = t + 256 * j;
        int row = c >> 3, seg = c & 7;
        br_doff[j] = OFF_BR + (uint32_t)(row * 144 + seg * 16);
        int gr = n0 + row; if (gr >= V) gr = V - 1;
        br_src[j] = ow + (size_t)gr * 1024 + seg * 4;
    }

    auto issue_stage = [&](int s) {
        const int k0 = s * KC;
        const uint32_t stg = (uint32_t)(s & 1);
        cp16(sbase + a_doff + stg * AS_STG, a_src + k0);
        #pragma unroll
        for (int j = 0; j < 4; j++)
            cp16(sbase + br_doff[j] + stg * BR_STG, br_src[j] + k0);
    };

    float acc[2][4][4];
    #pragma unroll
    for (int i = 0; i < 2; i++)
        #pragma unroll
        for (int j = 0; j < 4; j++)
            #pragma unroll
            for (int r = 0; r < 4; r++) acc[i][j][r] = 0.f;

    issue_stage(0); CP_COMMIT();
    issue_stage(1); CP_COMMIT();

    const int cv_row = t >> 1, cv_half = t & 1;

    for (int s = 0; s < H / KC; s++) {
        CP_WAIT1();
        __syncthreads();

        // convert Braw[s&1] (fp32) -> Bs[s&1] (bf16)
        {
            const unsigned char* src = dsm + OFF_BR + (uint32_t)(s & 1) * BR_STG
                                       + cv_row * 144 + cv_half * 64;
            const float4* s4 = (const float4*)src;
            float4 v0 = s4[0], v1 = s4[1], v2 = s4[2], v3 = s4[3];
            uint4 p0 = make_uint4(pack_bf2(v0.x, v0.y), pack_bf2(v0.z, v0.w),
                                  pack_bf2(v1.x, v1.y), pack_bf2(v1.z, v1.w));
            uint4 p1 = make_uint4(pack_bf2(v2.x, v2.y), pack_bf2(v2.z, v2.w),
                                  pack_bf2(v3.x, v3.y), pack_bf2(v3.z, v3.w));
            uint4* dst = (uint4*)(dsm + OFF_BS + (uint32_t)(s & 1) * BS_STG
                                  + cv_row * 80 + cv_half * 32);
            dst[0] = p0; dst[1] = p1;
        }
        __syncthreads();

        // compute from As[s&1] + Bs[s&1]
        {
            const unsigned char* As_p = dsm + OFF_AS + (uint32_t)(s & 1) * AS_STG;
            const unsigned char* Bs_p = dsm + OFF_BS + (uint32_t)(s & 1) * BS_STG;
            #pragma unroll
            for (int ks = 0; ks < 2; ks++) {
                unsigned afr[2][4];
                #pragma unroll
                for (int tm = 0; tm < 2; tm++) {
                    int row = wm * 32 + tm * 16 + ((lane >> 3) & 1) * 8 + (lane & 7);
                    int col = ks * 16 + (lane >> 4) * 8;
                    ldm_x4(afr[tm][0], afr[tm][1], afr[tm][2], afr[tm][3],
                           As_p + row * 80 + col * 2);
                }
                unsigned bfr[4][2];
                #pragma unroll
                for (int g = 0; g < 2; g++) {
                    int nrow = wn * 32 + g * 16 + (lane >> 4) * 8 + (lane & 7);
                    int col  = ks * 16 + ((lane >> 3) & 1) * 8;
                    unsigned r0, r1, r2, r3;
                    ldm_x4(r0, r1, r2, r3, Bs_p + nrow * 80 + col * 2);
                    bfr[g*2+0][0] = r0; bfr[g*2+0][1] = r1;
                    bfr[g*2+1][0] = r2; bfr[g*2+1][1] = r3;
                }
                #pragma unroll
                for (int tm = 0; tm < 2; tm++)
                    #pragma unroll
                    for (int tn = 0; tn < 4; tn++)
                        mma16816(acc[tm][tn], afr[tm], bfr[tn][0], bfr[tn][1]);
            }
        }
        __syncthreads();
        if (s + 2 < H / KC) issue_stage(s + 2);
        CP_COMMIT();
    }

    // epilogue: write logits + per-(row, block) online-softmax partials
    const float* sbias = (const float*)(dsm + OFF_BIAS);
    float2* part = (float2*)dsm;                 // reuse As region (2KB)
    const int mrow  = wm * 32 + (lane >> 2);
    const int ncol0 = n0 + wn * 32 + 2 * (lane & 3);

    float pmv[4], plv[4];
    #pragma unroll
    for (int i = 0; i < 4; i++) { pmv[i] = -1e30f; plv[i] = 0.f; }

    #pragma unroll
    for (int tm = 0; tm < 2; tm++) {
        #pragma unroll
        for (int tn = 0; tn < 4; tn++) {
            int r = mrow + tm * 16;
            int c = ncol0 + tn * 8;
            #pragma unroll
            for (int cc = 0; cc < 2; cc++) {
                if (c + cc < V) {
                    float bb = sbias[c + cc - n0];
                    float v0 = acc[tm][tn][cc]     + bb;    // row r
                    float v1 = acc[tm][tn][2 + cc] + bb;    // row r+8
                    dout[(size_t)r * V + c + cc]       = v0;
                    dout[(size_t)(r + 8) * V + c + cc] = v1;
                    int i0 = 2 * tm, i1 = 2 * tm + 1;
                    if (v0 > pmv[i0]) { plv[i0] *= __expf(pmv[i0] - v0); pmv[i0] = v0; }
                    plv[i0] += __expf(v0 - pmv[i0]);
                    if (v1 > pmv[i1]) { plv[i1] *= __expf(pmv[i1] - v1); pmv[i1] = v1; }
                    plv[i1] += __expf(v1 - pmv[i1]);
                }
            }
        }
    }
    // reduce across the 4 lanes sharing each row
    #pragma unroll
    for (int i = 0; i < 4; i++) {
        #pragma unroll
        for (int off = 1; off <= 2; off <<= 1) {
            float om = __shfl_xor_sync(0xffffffffu, pmv[i], off);
            float ol = __shfl_xor_sync(0xffffffffu, plv[i], off);
            float nm = fmaxf(pmv[i], om);
            plv[i] = plv[i] * __expf(pmv[i] - nm) + ol * __expf(om - nm);
            pmv[i] = nm;
        }
    }
    if ((lane & 3) == 0) {
        #pragma unroll
        for (int i = 0; i < 4; i++) {
            int row = wm * 32 + (lane >> 2) + (i & 1) * 8 + (i >> 1) * 16;
            part[row * 4 + wn] = make_float2(pmv[i], plv[i]);
        }
    }
    __syncthreads();
    if (t < 64) {
        float m = -1e30f, l = 0.f;
        #pragma unroll
        for (int k = 0; k < 4; k++) {
            float2 p = part[t * 4 + k];
            float nm = fmaxf(m, p.x);
            l = l * __expf(m - nm) + p.y * __expf(p.x - nm);
            m = nm;
        }
        g_plse[t * NBLKP + blockIdx.x] = make_float2(m, l);
    }
}

// ---------------- final: reduce lse partials (redundantly per CTA) + subtract ----------
constexpr int SUBSPAN = 6288;   // 8 * 6288 >= V
__global__ __launch_bounds__(256) void sub_final(float* __restrict__ dout)
{
    __shared__ float rm[256], rl[256];
    const int b = blockIdx.y, cx = blockIdx.x, t = threadIdx.x;
    float m = -1e30f, l = 0.f;
    for (int i = t; i < NBLK; i += 256) {
        float2 p = g_plse[b * NBLKP + i];
        float nm = fmaxf(m, p.x);
        l = l * __expf(m - nm) + p.y * __expf(p.x - nm);
        m = nm;
    }
    rm[t] = m; rl[t] = l; __syncthreads();
    for (int o = 128; o > 0; o >>= 1) {
        if (t < o) {
            float m2 = fmaxf(rm[t], rm[t + o]);
            rl[t] = rl[t] * __expf(rm[t] - m2) + rl[t + o] * __expf(rm[t + o] - m2);
            rm[t] = m2;
        }
        __syncthreads();
    }
    float lse = rm[0] + logf(rl[0]);
    float* row = dout + (size_t)b * V;
    int end = cx * SUBSPAN + SUBSPAN; if (end > V) end = V;
    for (int v = cx * SUBSPAN + t; v < end; v += 256) row[v] -= lse;
}

// ---------------- launch ----------------
extern "C" void kernel_launch(void* const* d_in, const int* in_sizes, int n_in,
                              void* d_out, int out_size)
{
    const int*   seq = (const int*)  d_in[0];
    const float* lh  = (const float*)d_in[1];
    const float* enc = (const float*)d_in[2];
    const float* emb = (const float*)d_in[3];
    const float* wih = (const float*)d_in[4];
    const float* whh = (const float*)d_in[5];
    const float* bih = (const float*)d_in[6];
    const float* bhh = (const float*)d_in[7];
    const float* cw  = (const float*)d_in[8];
    const float* cb  = (const float*)d_in[9];
    const float* ow  = (const float*)d_in[10];
    const float* ob  = (const float*)d_in[11];
    float* dout = (float*)d_out;
    (void)in_sizes; (void)n_in; (void)out_size;

    static bool attr_done = false;
    if (!attr_done) {
        cudaFuncSetAttribute(out_gemm_cp,
                             cudaFuncAttributeMaxDynamicSharedMemorySize, OUT_SMEM);
        cudaFuncSetAttribute(mma_small<0, 3*H, H, SPL>,
                             cudaFuncAttributeMaxDynamicSharedMemorySize, SMALL_SMEM);
        cudaFuncSetAttribute(mma_small<2, H, 2*H, CATSPL>,
                             cudaFuncAttributeMaxDynamicSharedMemorySize, SMALL_SMEM);
        attr_done = true;
    }

    // GRU gate GEMMs on tensor cores (z=0: emb path, z=1: hidden path)
    mma_small<0, 3*H, H, SPL><<<dim3(24, SPL, 2), 256, SMALL_SMEM>>>(seq, emb, lh, wih, whh);
    gru_gates<<<256, 256>>>(lh, bih, bhh, dout);

    // attention (single HBM pass)
    attn_fused<<<dim3(16, 64), 256>>>(enc);
    attn_combine<<<64, 256>>>();

    // concat GEMM on tensor cores + tanh -> bf16
    mma_small<2, H, 2*H, CATSPL><<<dim3(8, CATSPL), 256, SMALL_SMEM>>>(nullptr, nullptr, nullptr, cw, nullptr);
    cat_combine<<<256, 256>>>(cb);

    // output GEMM (mma.sync + cp.async, 3 CTA/SM) -> logits + lse partials
    out_gemm_cp<<<NBLK, 256, OUT_SMEM>>>(ow, ob, dout);

    // reduce partials + subtract (full-chip)
    sub_final<<<dim3(8, 64), 256>>>(dout);
}